// round 12
// baseline (speedup 1.0000x reference)
#include <cuda_runtime.h>
#include <cstdint>

// Problem constants
#define Bn  1024
#define Sn  128
#define En  256
#define Hn  8
#define Dn  64
#define HDn 512

// Scratch (tf32 bit patterns in float arrays): Q,K,V per-(b,h) [128x64] tiles,
// Xt = pre-converted inputs, Wt = transposed + converted weights.
__device__ float g_Q[67108864];
__device__ float g_K[67108864];
__device__ float g_V[67108864];
__device__ float g_Xt[33554432];
__device__ float g_Wt[2048 * 256];

// ---------------------------------------------------------------------------
// Helpers. tcgen05 unusable (harness PTX target sm_103, no 'a' suffix) -> the
// tensor path is arch-portable mma.sync (HMMA on sm_103a).
// ---------------------------------------------------------------------------
__device__ __forceinline__ uint32_t smem_u32(const void* p) {
    uint32_t a;
    asm("{ .reg .u64 t; cvta.to.shared.u64 t, %1; cvt.u32.u64 %0, t; }"
        : "=r"(a) : "l"(p));
    return a;
}
__device__ __forceinline__ uint32_t f2tf32(float x) {
    uint32_t r;
    asm("cvt.rna.tf32.f32 %0, %1;" : "=r"(r) : "f"(x));
    return r;
}
__device__ __forceinline__ void mma_tf32(float* c,
                                         const uint32_t* a,
                                         const uint32_t* b) {
    asm volatile(
        "mma.sync.aligned.m16n8k8.row.col.f32.tf32.tf32.f32 "
        "{%0,%1,%2,%3}, {%4,%5,%6,%7}, {%8,%9}, {%0,%1,%2,%3};"
        : "+f"(c[0]), "+f"(c[1]), "+f"(c[2]), "+f"(c[3])
        : "r"(a[0]), "r"(a[1]), "r"(a[2]), "r"(a[3]),
          "r"(b[0]), "r"(b[1]));
}
__device__ __forceinline__ void cpa16(uint32_t saddr, const void* g) {
    asm volatile("cp.async.cg.shared.global [%0], [%1], 16;"
                 :: "r"(saddr), "l"(g) : "memory");
}
#define CP_COMMIT() asm volatile("cp.async.commit_group;" ::: "memory")
#define CP_WAIT(n)  asm volatile("cp.async.wait_group %0;" :: "n"(n) : "memory")

// =============================================================================
// Kernel 0a: convert X -> tf32 bits (RNA) in g_Xt.
// =============================================================================
__global__ void xconv_kernel(const float4* __restrict__ X)
{
    uint4* dst = (uint4*)g_Xt;
#pragma unroll
    for (int j = 0; j < 4; ++j) {
        const size_t i = (size_t)blockIdx.x * 1024 + j * 256 + threadIdx.x;
        float4 v = X[i];
        dst[i] = make_uint4(f2tf32(v.x), f2tf32(v.y), f2tf32(v.z), f2tf32(v.w));
    }
}

// =============================================================================
// Kernel 0b: weight transpose + tf32 convert. Wt[w*512 + n][k] = tf32(W_w[k][n])
// =============================================================================
__global__ void wtrans_kernel(const float* __restrict__ Wq,
                              const float* __restrict__ Wk,
                              const float* __restrict__ Wv,
                              const float* __restrict__ Wr)
{
    __shared__ float t[32][33];
    const int wsel = blockIdx.z;
    const float* W = (wsel == 0) ? Wq : (wsel == 1) ? Wk : (wsel == 2) ? Wv : Wr;
    const int n0 = blockIdx.x * 32, k0 = blockIdx.y * 32;
    const int tx = threadIdx.x, ty = threadIdx.y;
#pragma unroll
    for (int i = 0; i < 32; i += 8)
        t[ty + i][tx] = W[(size_t)(k0 + ty + i) * HDn + n0 + tx];
    __syncthreads();
    uint32_t* Wt = (uint32_t*)g_Wt;
#pragma unroll
    for (int i = 0; i < 32; i += 8)
        Wt[(size_t)(wsel * HDn + n0 + ty + i) * En + k0 + tx] = f2tf32(t[tx][ty + i]);
}

// =============================================================================
// Kernel 1: PERSISTENT tf32 mma.sync projection GEMM. 304 CTAs (2/SM), 128
// threads, 4 warps, C-tile 128x128, warp tile 64x64 (4mt x 8nt fragments).
// Each CTA loops over ~54 tiles; the cp.async chunk stream is FLAT across
// tile boundaries (issue cursor leads compute by 2 chunks), so pipeline fill
// happens once per CTA and the epilogue overlaps the next tile's prefetch.
// Wait discipline: wait_group(1) while issuing, wait_group(0) once the issue
// cursor is exhausted (covers the final chunks). Slot safety: the sync at
// chunk i guarantees slot (i-1)%3 is free for issue i+2 (as before).
// Accumulation order per output element unchanged -> bit-identical results.
// =============================================================================
constexpr int PP = 36;                       // smem pitch (u32), conflict-free
constexpr int CHUNK_U = 128 * PP;            // 4608 u32 per matrix per chunk
constexpr int SLOT_U  = 2 * CHUNK_U;         // 9216 u32 = 36864 B
constexpr int NTILES  = 16384;               // 16 (bx) x 1024 (b)
constexpr int PROJ_GRID = 304;               // 2 per SM (152 SMs)

__global__ __launch_bounds__(128)
void proj_mma(float* __restrict__ out)
{
    extern __shared__ uint32_t sm[];
    const uint32_t sb = smem_u32(sm);

    const int tid  = threadIdx.x;
    const int wid  = tid >> 5;      // 0..3
    const int lane = tid & 31;
    const int g    = lane >> 2;
    const int tg   = lane & 3;

    const int wm = wid >> 1;        // 0..1 -> m base wm*64
    const int wn = wid & 1;         // 0..1 -> n base wn*64

    const float4* W4 = (const float4*)g_Wt;

    // cp.async coords: A chunk = 1024 float4 (128 rows x 8), 8/thread; B same.
    int lrow[8], lkq[8];
    uint32_t soff[8];
#pragma unroll
    for (int i = 0; i < 8; ++i) {
        const int f4 = tid + i * 128;
        lrow[i] = f4 >> 3;
        lkq[i]  = f4 & 7;
        soff[i] = (uint32_t)(lrow[i] * PP + lkq[i] * 4) * 4;
    }

    // Issue cursor: next (tile, chunk) to fetch, and its slot.
    int nxT = blockIdx.x;           // tile index (bx = t & 15, b = t >> 4)
    int nxC = 0;
    int islot = 0;

    auto issue_next = [&]() {
        if (nxT < NTILES) {
            const int bx = nxT & 15;
            const int b  = nxT >> 4;
            const int nbase = bx * 128;
            const float4* A4 = (const float4*)(g_Xt + (size_t)b * Sn * En);
            const uint32_t a_s = sb + (uint32_t)islot * SLOT_U * 4;
            const uint32_t b_s = a_s + CHUNK_U * 4;
            const int c = nxC;
#pragma unroll
            for (int i = 0; i < 8; ++i) {
                cpa16(a_s + soff[i], A4 + lrow[i] * 64 + c * 8 + lkq[i]);
                cpa16(b_s + soff[i], W4 + (size_t)(nbase + lrow[i]) * 64 + c * 8 + lkq[i]);
            }
            CP_COMMIT();
            islot = (islot == 2) ? 0 : islot + 1;
            if (++nxC == 8) { nxC = 0; nxT += PROJ_GRID; }
        }
    };

    issue_next();
    issue_next();

    int cslot = 0;

#pragma unroll 1
    for (int t = blockIdx.x; t < NTILES; t += PROJ_GRID) {
        const int bx    = t & 15;
        const int b     = t >> 4;
        const int w     = bx >> 2;
        const int ncol0 = (bx & 3) * 128;

        float acc[4][8][4];
#pragma unroll
        for (int mt = 0; mt < 4; ++mt)
#pragma unroll
            for (int nt = 0; nt < 8; ++nt)
#pragma unroll
                for (int j = 0; j < 4; ++j) acc[mt][nt][j] = 0.f;

#pragma unroll 1
        for (int c = 0; c < 8; ++c) {
            if (nxT >= NTILES) { CP_WAIT(0); } else { CP_WAIT(1); }
            __syncthreads();            // chunk visible; slot (i-1)%3 reusable
            issue_next();

            const uint32_t* SA = sm + cslot * SLOT_U;
            const uint32_t* SB = SA + CHUNK_U;
            cslot = (cslot == 2) ? 0 : cslot + 1;
#pragma unroll
            for (int ks = 0; ks < 4; ++ks) {
                const int k0 = ks * 8;
                uint32_t af[4][4], bf[8][2];
#pragma unroll
                for (int mt = 0; mt < 4; ++mt) {
                    const int base = (wm * 64 + mt * 16 + g) * PP + k0 + tg;
                    af[mt][0] = SA[base];
                    af[mt][1] = SA[base + 8 * PP];
                    af[mt][2] = SA[base + 4];
                    af[mt][3] = SA[base + 8 * PP + 4];
                }
#pragma unroll
                for (int nt = 0; nt < 8; ++nt) {
                    const int nb = (wn * 64 + nt * 8 + g) * PP + k0 + tg;
                    bf[nt][0] = SB[nb];
                    bf[nt][1] = SB[nb + 4];
                }
#pragma unroll
                for (int mt = 0; mt < 4; ++mt)
#pragma unroll
                    for (int nt = 0; nt < 8; ++nt)
                        mma_tf32(acc[mt][nt], af[mt], bf[nt]);
            }
        }

        // Epilogue (no smem use -> overlaps in-flight prefetch of next tile).
        // Q/K/V as tf32 bits, R as fp32.
#pragma unroll
        for (int mt = 0; mt < 4; ++mt) {
            const int row = wm * 64 + mt * 16 + g;
#pragma unroll
            for (int nt = 0; nt < 8; ++nt) {
                const int cl = wn * 64 + nt * 8 + tg * 2;
                const int nw = ncol0 + cl;
                if (w < 3) {
                    float* G = (w == 0) ? g_Q : (w == 1) ? g_K : g_V;
                    const int h  = nw >> 6;
                    const int d0 = nw & 63;
                    uint32_t* dst = (uint32_t*)(G + (((size_t)(b * Hn + h) * Sn + row) * Dn + d0));
                    *(uint2*)dst            = make_uint2(f2tf32(acc[mt][nt][0]), f2tf32(acc[mt][nt][1]));
                    *(uint2*)(dst + 8 * Dn) = make_uint2(f2tf32(acc[mt][nt][2]), f2tf32(acc[mt][nt][3]));
                } else {
                    float* dst = out + ((size_t)b * Sn + row) * HDn + nw;
                    *(float2*)dst             = make_float2(acc[mt][nt][0], acc[mt][nt][1]);
                    *(float2*)(dst + 8 * HDn) = make_float2(acc[mt][nt][2], acc[mt][nt][3]);
                }
            }
        }
    }
}

// =============================================================================
// Kernel 2: tf32 mma.sync attention (round-11 version, unchanged).
// One CTA per (b,h), 256 threads, 8 warps; batch order reversed for L2 reuse;
// residual prefetched into registers; pitches SQ/SK 68, SV 72, SP 132.
// =============================================================================
constexpr int PK  = 68;
constexpr int PV  = 72;
constexpr int PPs = 132;

__global__ __launch_bounds__(256)
void attn_mma(float* __restrict__ out)
{
    extern __shared__ uint32_t smu[];
    uint32_t* SQ = smu;                         // [128][68]
    uint32_t* SK = smu + 128 * PK;              // [128][68]
    uint32_t* SV = smu + 2 * 128 * PK;          // [128][72]
    uint32_t* SP = smu;                         // [128][132] overlays SQ+SK

    const int tid  = threadIdx.x;
    const int wid  = tid >> 5;
    const int lane = tid & 31;
    const int g    = lane >> 2;
    const int tg   = lane & 3;
    const int h = blockIdx.x;
    const int b = (Bn - 1) - blockIdx.y;        // reversed: reuse proj's L2 tail

    const size_t base = ((size_t)(b * Hn + h) * Sn) * Dn;
    const float4* Qg = (const float4*)(g_Q + base);
    const float4* Kg = (const float4*)(g_K + base);
    const float4* Vg = (const float4*)(g_V + base);

    const uint32_t sb = smem_u32(smu);
    const uint32_t SKo = 128 * PK * 4;
    const uint32_t SVo = 2 * 128 * PK * 4;

    // ---- stage Q,K,V raw (already tf32 bits) via cp.async ----
#pragma unroll
    for (int i = 0; i < 8; ++i) {
        const int f4  = tid + i * 256;
        const int row = f4 >> 4;
        const int c4  = (f4 & 15) * 4;
        cpa16(sb + (uint32_t)(row * PK + c4) * 4,       Qg + f4);
        cpa16(sb + SKo + (uint32_t)(row * PK + c4) * 4, Kg + f4);
        cpa16(sb + SVo + (uint32_t)(row * PV + c4) * 4, Vg + f4);
    }
    CP_COMMIT();
    CP_WAIT(0);
    __syncthreads();

    // ---- S = Q K^T ----
    float acc[16][4];
#pragma unroll
    for (int nt = 0; nt < 16; ++nt)
#pragma unroll
        for (int j = 0; j < 4; ++j) acc[nt][j] = 0.f;

    const uint32_t* Arow = SQ + (wid * 16 + g) * PK;
#pragma unroll
    for (int ks = 0; ks < 8; ++ks) {
        const int k0 = ks * 8;
        uint32_t af[4];
        af[0] = Arow[k0 + tg];
        af[1] = Arow[8 * PK + k0 + tg];
        af[2] = Arow[k0 + tg + 4];
        af[3] = Arow[8 * PK + k0 + tg + 4];
#pragma unroll
        for (int nt = 0; nt < 16; ++nt) {
            const uint32_t* Bp = SK + (nt * 8 + g) * PK + k0 + tg;
            uint32_t bf[2] = { Bp[0], Bp[4] };
            mma_tf32(acc[nt], af, bf);
        }
    }

    // ---- softmax rows r0 = wid*16+g, r1 = r0+8 (quad-local shfl) ----
    const int r0 = wid * 16 + g;
    float m0 = -1e30f, m1 = -1e30f;
#pragma unroll
    for (int nt = 0; nt < 16; ++nt) {
        m0 = fmaxf(m0, fmaxf(acc[nt][0], acc[nt][1]));
        m1 = fmaxf(m1, fmaxf(acc[nt][2], acc[nt][3]));
    }
#pragma unroll
    for (int off = 2; off >= 1; off >>= 1) {
        m0 = fmaxf(m0, __shfl_xor_sync(0xffffffffu, m0, off));
        m1 = fmaxf(m1, __shfl_xor_sync(0xffffffffu, m1, off));
    }
    float s0 = 0.f, s1 = 0.f;
#pragma unroll
    for (int nt = 0; nt < 16; ++nt) {
        acc[nt][0] = __expf(acc[nt][0] - m0);
        acc[nt][1] = __expf(acc[nt][1] - m0);
        acc[nt][2] = __expf(acc[nt][2] - m1);
        acc[nt][3] = __expf(acc[nt][3] - m1);
        s0 += acc[nt][0] + acc[nt][1];
        s1 += acc[nt][2] + acc[nt][3];
    }
#pragma unroll
    for (int off = 2; off >= 1; off >>= 1) {
        s0 += __shfl_xor_sync(0xffffffffu, s0, off);
        s1 += __shfl_xor_sync(0xffffffffu, s1, off);
    }
    const float inv0 = 1.0f / s0;
    const float inv1 = 1.0f / s1;

    // ---- prefetch residual (hides LDG latency under the PV loop) ----
    float* op = out + ((size_t)b * Sn) * HDn + h * Dn;
    float2 res0[8], res1[8];
#pragma unroll
    for (int nt = 0; nt < 8; ++nt) {
        const int d = nt * 8 + tg * 2;
        res0[nt] = *(const float2*)(op + (size_t)r0 * HDn + d);
        res1[nt] = *(const float2*)(op + (size_t)(r0 + 8) * HDn + d);
    }

    __syncthreads();   // all warps done reading SQ/SK before SP overlays them

#pragma unroll
    for (int nt = 0; nt < 16; ++nt) {
        const int cl = nt * 8 + tg * 2;
        *(uint2*)&SP[r0 * PPs + cl] =
            make_uint2(f2tf32(acc[nt][0]), f2tf32(acc[nt][1]));
        *(uint2*)&SP[(r0 + 8) * PPs + cl] =
            make_uint2(f2tf32(acc[nt][2]), f2tf32(acc[nt][3]));
    }
    __syncthreads();

    // ---- O = P V ----
    float oacc[8][4];
#pragma unroll
    for (int nt = 0; nt < 8; ++nt)
#pragma unroll
        for (int j = 0; j < 4; ++j) oacc[nt][j] = 0.f;

    const uint32_t* Ap = SP + (wid * 16 + g) * PPs;
#pragma unroll
    for (int ks = 0; ks < 16; ++ks) {
        const int k0 = ks * 8;
        uint32_t af[4];
        af[0] = Ap[k0 + tg];
        af[1] = Ap[8 * PPs + k0 + tg];
        af[2] = Ap[k0 + tg + 4];
        af[3] = Ap[8 * PPs + k0 + tg + 4];
#pragma unroll
        for (int nt = 0; nt < 8; ++nt) {
            uint32_t bf[2];
            bf[0] = SV[(k0 + tg) * PV + nt * 8 + g];
            bf[1] = SV[(k0 + tg + 4) * PV + nt * 8 + g];
            mma_tf32(oacc[nt], af, bf);
        }
    }

    // ---- epilogue: normalize, +residual (prefetched), ReLU ----
#pragma unroll
    for (int nt = 0; nt < 8; ++nt) {
        const int d = nt * 8 + tg * 2;
        float x0 = res0[nt].x + oacc[nt][0] * inv0;
        float x1 = res0[nt].y + oacc[nt][1] * inv0;
        float x2 = res1[nt].x + oacc[nt][2] * inv1;
        float x3 = res1[nt].y + oacc[nt][3] * inv1;
        *(float2*)(op + (size_t)r0 * HDn + d) =
            make_float2(fmaxf(x0, 0.f), fmaxf(x1, 0.f));
        *(float2*)(op + (size_t)(r0 + 8) * HDn + d) =
            make_float2(fmaxf(x2, 0.f), fmaxf(x3, 0.f));
    }
}

// =============================================================================
extern "C" void kernel_launch(void* const* d_in, const int* in_sizes, int n_in,
                              void* d_out, int out_size)
{
    const float* X  = (const float*)d_in[0];
    const float* Wq = (const float*)d_in[1];
    const float* Wk = (const float*)d_in[2];
    const float* Wv = (const float*)d_in[3];
    const float* Wr = (const float*)d_in[4];
    float* out = (float*)d_out;

    const int proj_smem = 3 * SLOT_U * (int)sizeof(uint32_t);                // 110592
    const int attn_smem = (2 * 128 * PK + 128 * PV) * (int)sizeof(uint32_t); // 106496
    cudaFuncSetAttribute(proj_mma,
                         cudaFuncAttributeMaxDynamicSharedMemorySize, proj_smem);
    cudaFuncSetAttribute(attn_mma,
                         cudaFuncAttributeMaxDynamicSharedMemorySize, attn_smem);

    xconv_kernel<<<8192, 256>>>((const float4*)X);
    wtrans_kernel<<<dim3(16, 8, 4), dim3(32, 8)>>>(Wq, Wk, Wv, Wr);
    proj_mma<<<PROJ_GRID, 128, proj_smem>>>(out);
    attn_mma<<<dim3(8, 1024), 256, attn_smem>>>(out);
}

// round 13
// speedup vs baseline: 1.1843x; 1.1843x over previous
#include <cuda_runtime.h>
#include <cstdint>

// Problem constants
#define Bn  1024
#define Sn  128
#define En  256
#define Hn  8
#define Dn  64
#define HDn 512

// Scratch (tf32 bit patterns in float arrays).
// g_Xt: X pre-converted AND pre-permuted into mma-fragment order:
//   [b][chunk c:8][frag f:32][lane:32][word j:4]  (4096 u32 per chunk)
//   f = mi*4+ks (mi = m-tile 0..7, ks = k-subtile 0..3), lane = g*4+tg,
//   j: {(m0+g,k0+tg), (m0+g+8,k0+tg), (m0+g,k0+tg+4), (m0+g+8,k0+tg+4)}
// g_Wt: weights transposed+converted+permuted:
//   [bx:16][chunk c:8][frag f:32][lane:32][word j:4]
//   f = pb*4+ks (pb = n-pair-block 0..7), j packs two n-tiles:
//   {(n0+16pb+g,k0+tg), (n0+16pb+g,k0+tg+4), (n0+16pb+8+g,k0+tg), (n0+16pb+8+g,k0+tg+4)}
__device__ float g_Q[67108864];
__device__ float g_K[67108864];
__device__ float g_V[67108864];
__device__ float g_Xt[33554432];          // 1024*8*4096
__device__ float g_Wt[524288];            // 16*8*4096

// ---------------------------------------------------------------------------
// Helpers. tcgen05 unusable (harness PTX target sm_103, no 'a' suffix) -> the
// tensor path is arch-portable mma.sync (HMMA on sm_103a).
// ---------------------------------------------------------------------------
__device__ __forceinline__ uint32_t smem_u32(const void* p) {
    uint32_t a;
    asm("{ .reg .u64 t; cvta.to.shared.u64 t, %1; cvt.u32.u64 %0, t; }"
        : "=r"(a) : "l"(p));
    return a;
}
__device__ __forceinline__ uint32_t f2tf32(float x) {
    uint32_t r;
    asm("cvt.rna.tf32.f32 %0, %1;" : "=r"(r) : "f"(x));
    return r;
}
__device__ __forceinline__ void mma_tf32(float* c,
                                         const uint32_t* a,
                                         const uint32_t* b) {
    asm volatile(
        "mma.sync.aligned.m16n8k8.row.col.f32.tf32.tf32.f32 "
        "{%0,%1,%2,%3}, {%4,%5,%6,%7}, {%8,%9}, {%0,%1,%2,%3};"
        : "+f"(c[0]), "+f"(c[1]), "+f"(c[2]), "+f"(c[3])
        : "r"(a[0]), "r"(a[1]), "r"(a[2]), "r"(a[3]),
          "r"(b[0]), "r"(b[1]));
}
__device__ __forceinline__ void cpa16(uint32_t saddr, const void* g) {
    asm volatile("cp.async.cg.shared.global [%0], [%1], 16;"
                 :: "r"(saddr), "l"(g) : "memory");
}
#define CP_COMMIT() asm volatile("cp.async.commit_group;" ::: "memory")
#define CP_WAIT(n)  asm volatile("cp.async.wait_group %0;" :: "n"(n) : "memory")

// =============================================================================
// Kernel 0a: convert X -> tf32 bits, permuted into fragment-major layout.
// grid (8, 1024) = (c, b), 256 threads, 4 uint4 outputs/thread.
// =============================================================================
__global__ void xconv_kernel(const float* __restrict__ X)
{
    const int c = blockIdx.x;
    const int b = blockIdx.y;
    const float* src = X + (size_t)b * Sn * En;
    uint4* dst = (uint4*)((uint32_t*)g_Xt + ((size_t)b * 8 + c) * 4096);

#pragma unroll
    for (int i = 0; i < 4; ++i) {
        const int o  = threadIdx.x + i * 256;   // 0..1023
        const int f  = o >> 5;
        const int l  = o & 31;
        const int mi = f >> 2, ks = f & 3;
        const int g  = l >> 2, tg = l & 3;
        const int m  = mi * 16 + g;
        const int k  = c * 32 + ks * 8 + tg;
        uint4 v;
        v.x = f2tf32(src[(size_t)m * En + k]);
        v.y = f2tf32(src[(size_t)(m + 8) * En + k]);
        v.z = f2tf32(src[(size_t)m * En + k + 4]);
        v.w = f2tf32(src[(size_t)(m + 8) * En + k + 4]);
        dst[o] = v;
    }
}

// =============================================================================
// Kernel 0b: weight transpose + convert + fragment-major permute.
// grid (8, 16) = (c, bx), 256 threads, 4 uint4/thread.
// =============================================================================
__global__ void wtrans_kernel(const float* __restrict__ Wq,
                              const float* __restrict__ Wk,
                              const float* __restrict__ Wv,
                              const float* __restrict__ Wr)
{
    const int c  = blockIdx.x;
    const int bx = blockIdx.y;
    const int w  = bx >> 2;
    const int ncol0 = (bx & 3) * 128;
    const float* W = (w == 0) ? Wq : (w == 1) ? Wk : (w == 2) ? Wv : Wr;
    uint4* dst = (uint4*)((uint32_t*)g_Wt + ((size_t)bx * 8 + c) * 4096);

#pragma unroll
    for (int i = 0; i < 4; ++i) {
        const int o  = threadIdx.x + i * 256;
        const int f  = o >> 5;
        const int l  = o & 31;
        const int pb = f >> 2, ks = f & 3;
        const int g  = l >> 2, tg = l & 3;
        const int n0 = pb * 16 + g;             // local n row (within tile)
        const int k  = c * 32 + ks * 8 + tg;
        // j: {(n0,k), (n0,k+4), (n0+8,k), (n0+8,k+4)}  (bf pair order)
        uint4 v;
        v.x = f2tf32(W[(size_t)k * HDn + ncol0 + n0]);
        v.y = f2tf32(W[(size_t)(k + 4) * HDn + ncol0 + n0]);
        v.z = f2tf32(W[(size_t)k * HDn + ncol0 + n0 + 8]);
        v.w = f2tf32(W[(size_t)(k + 4) * HDn + ncol0 + n0 + 8]);
        dst[o] = v;
    }
}

// =============================================================================
// Kernel 1: tf32 mma.sync projection GEMM (round-11 structure restored:
// grid (16,1024), 128 threads, 4 warps, warp tile 64x64, 3-stage cp.async,
// one __syncthreads per chunk, 2 CTAs/SM) with fragment-major operands:
// every A fragment and B fragment-pair is ONE conflict-free LDS.128.
// Inner loop per chunk per thread: 32 LDS.128 + 128 MMA (was 128 LDS.32).
// Same values, same accumulation order -> bit-identical results.
// =============================================================================
constexpr int CHUNK_U = 4096;                // u32 per matrix per chunk (16 KB)
constexpr int SLOT_U  = 2 * CHUNK_U;         // 8192 u32 = 32 KB
// 3 slots = 96 KB -> 2 CTAs/SM

__global__ __launch_bounds__(128)
void proj_mma(float* __restrict__ out)
{
    extern __shared__ uint32_t sm[];
    const uint32_t sb = smem_u32(sm);

    const int tid  = threadIdx.x;
    const int wid  = tid >> 5;      // 0..3
    const int lane = tid & 31;
    const int bx   = blockIdx.x;
    const int b    = blockIdx.y;
    const int w    = bx >> 2;
    const int ncol0 = (bx & 3) * 128;
    const int g    = lane >> 2;
    const int tg   = lane & 3;

    const int wm = wid >> 1;        // 0..1 -> m base wm*64
    const int wn = wid & 1;         // 0..1 -> n base wn*64

    const uint4* Ag = (const uint4*)((const uint32_t*)g_Xt + (size_t)b * 8 * 4096);
    const uint4* Bg = (const uint4*)((const uint32_t*)g_Wt + (size_t)bx * 8 * 4096);

    auto issue = [&](int c) {
        const int slot = c % 3;
        const uint32_t a_s = sb + (uint32_t)slot * SLOT_U * 4;
        const uint32_t b_s = a_s + CHUNK_U * 4;
        const uint4* ag = Ag + c * 1024;
        const uint4* bg = Bg + c * 1024;
#pragma unroll
        for (int i = 0; i < 8; ++i) {
            const int o = tid + i * 128;        // 0..1023 uint4s
            cpa16(a_s + o * 16, ag + o);
            cpa16(b_s + o * 16, bg + o);
        }
        CP_COMMIT();
    };

    issue(0);
    issue(1);

    float acc[4][8][4];
#pragma unroll
    for (int mt = 0; mt < 4; ++mt)
#pragma unroll
        for (int nt = 0; nt < 8; ++nt)
#pragma unroll
            for (int j = 0; j < 4; ++j) acc[mt][nt][j] = 0.f;

#pragma unroll 1
    for (int c = 0; c < 8; ++c) {
        const int slot = c % 3;
        if (c < 7) { CP_WAIT(1); } else { CP_WAIT(0); }
        __syncthreads();            // chunk c visible; slot (c-1)%3 reusable
        if (c < 6) issue(c + 2);

        const uint32_t* SA = sm + slot * SLOT_U;
        const uint32_t* SB = SA + CHUNK_U;
#pragma unroll
        for (int ks = 0; ks < 4; ++ks) {
            uint32_t af[4][4], bf[8][2];
#pragma unroll
            for (int mt = 0; mt < 4; ++mt) {
                uint4 a = *(const uint4*)(SA + (((wm * 4 + mt) * 4 + ks) * 32 + lane) * 4);
                af[mt][0] = a.x; af[mt][1] = a.y; af[mt][2] = a.z; af[mt][3] = a.w;
            }
#pragma unroll
            for (int p = 0; p < 4; ++p) {
                uint4 bq = *(const uint4*)(SB + (((wn * 4 + p) * 4 + ks) * 32 + lane) * 4);
                bf[2 * p][0]     = bq.x; bf[2 * p][1]     = bq.y;
                bf[2 * p + 1][0] = bq.z; bf[2 * p + 1][1] = bq.w;
            }
#pragma unroll
            for (int mt = 0; mt < 4; ++mt)
#pragma unroll
                for (int nt = 0; nt < 8; ++nt)
                    mma_tf32(acc[mt][nt], af[mt], bf[nt]);
        }
    }

    // Epilogue: Q/K/V as tf32 bits, R as fp32.
#pragma unroll
    for (int mt = 0; mt < 4; ++mt) {
        const int row = wm * 64 + mt * 16 + g;
#pragma unroll
        for (int nt = 0; nt < 8; ++nt) {
            const int cl = wn * 64 + nt * 8 + tg * 2;
            const int nw = ncol0 + cl;
            if (w < 3) {
                float* G = (w == 0) ? g_Q : (w == 1) ? g_K : g_V;
                const int h  = nw >> 6;
                const int d0 = nw & 63;
                uint32_t* dst = (uint32_t*)(G + (((size_t)(b * Hn + h) * Sn + row) * Dn + d0));
                *(uint2*)dst            = make_uint2(f2tf32(acc[mt][nt][0]), f2tf32(acc[mt][nt][1]));
                *(uint2*)(dst + 8 * Dn) = make_uint2(f2tf32(acc[mt][nt][2]), f2tf32(acc[mt][nt][3]));
            } else {
                float* dst = out + ((size_t)b * Sn + row) * HDn + nw;
                *(float2*)dst             = make_float2(acc[mt][nt][0], acc[mt][nt][1]);
                *(float2*)(dst + 8 * HDn) = make_float2(acc[mt][nt][2], acc[mt][nt][3]);
            }
        }
    }
}

// =============================================================================
// Kernel 2: tf32 mma.sync attention (round-11 version, unchanged).
// One CTA per (b,h), 256 threads, 8 warps; batch order reversed for L2 reuse;
// residual prefetched into registers; pitches SQ/SK 68, SV 72, SP 132.
// =============================================================================
constexpr int PK  = 68;
constexpr int PV  = 72;
constexpr int PPs = 132;

__global__ __launch_bounds__(256)
void attn_mma(float* __restrict__ out)
{
    extern __shared__ uint32_t smu[];
    uint32_t* SQ = smu;                         // [128][68]
    uint32_t* SK = smu + 128 * PK;              // [128][68]
    uint32_t* SV = smu + 2 * 128 * PK;          // [128][72]
    uint32_t* SP = smu;                         // [128][132] overlays SQ+SK

    const int tid  = threadIdx.x;
    const int wid  = tid >> 5;
    const int lane = tid & 31;
    const int g    = lane >> 2;
    const int tg   = lane & 3;
    const int h = blockIdx.x;
    const int b = (Bn - 1) - blockIdx.y;        // reversed: reuse proj's L2 tail

    const size_t base = ((size_t)(b * Hn + h) * Sn) * Dn;
    const float4* Qg = (const float4*)(g_Q + base);
    const float4* Kg = (const float4*)(g_K + base);
    const float4* Vg = (const float4*)(g_V + base);

    const uint32_t sb = smem_u32(smu);
    const uint32_t SKo = 128 * PK * 4;
    const uint32_t SVo = 2 * 128 * PK * 4;

    // ---- stage Q,K,V raw (already tf32 bits) via cp.async ----
#pragma unroll
    for (int i = 0; i < 8; ++i) {
        const int f4  = tid + i * 256;
        const int row = f4 >> 4;
        const int c4  = (f4 & 15) * 4;
        cpa16(sb + (uint32_t)(row * PK + c4) * 4,       Qg + f4);
        cpa16(sb + SKo + (uint32_t)(row * PK + c4) * 4, Kg + f4);
        cpa16(sb + SVo + (uint32_t)(row * PV + c4) * 4, Vg + f4);
    }
    CP_COMMIT();
    CP_WAIT(0);
    __syncthreads();

    // ---- S = Q K^T ----
    float acc[16][4];
#pragma unroll
    for (int nt = 0; nt < 16; ++nt)
#pragma unroll
        for (int j = 0; j < 4; ++j) acc[nt][j] = 0.f;

    const uint32_t* Arow = SQ + (wid * 16 + g) * PK;
#pragma unroll
    for (int ks = 0; ks < 8; ++ks) {
        const int k0 = ks * 8;
        uint32_t af[4];
        af[0] = Arow[k0 + tg];
        af[1] = Arow[8 * PK + k0 + tg];
        af[2] = Arow[k0 + tg + 4];
        af[3] = Arow[8 * PK + k0 + tg + 4];
#pragma unroll
        for (int nt = 0; nt < 16; ++nt) {
            const uint32_t* Bp = SK + (nt * 8 + g) * PK + k0 + tg;
            uint32_t bf[2] = { Bp[0], Bp[4] };
            mma_tf32(acc[nt], af, bf);
        }
    }

    // ---- softmax rows r0 = wid*16+g, r1 = r0+8 (quad-local shfl) ----
    const int r0 = wid * 16 + g;
    float m0 = -1e30f, m1 = -1e30f;
#pragma unroll
    for (int nt = 0; nt < 16; ++nt) {
        m0 = fmaxf(m0, fmaxf(acc[nt][0], acc[nt][1]));
        m1 = fmaxf(m1, fmaxf(acc[nt][2], acc[nt][3]));
    }
#pragma unroll
    for (int off = 2; off >= 1; off >>= 1) {
        m0 = fmaxf(m0, __shfl_xor_sync(0xffffffffu, m0, off));
        m1 = fmaxf(m1, __shfl_xor_sync(0xffffffffu, m1, off));
    }
    float s0 = 0.f, s1 = 0.f;
#pragma unroll
    for (int nt = 0; nt < 16; ++nt) {
        acc[nt][0] = __expf(acc[nt][0] - m0);
        acc[nt][1] = __expf(acc[nt][1] - m0);
        acc[nt][2] = __expf(acc[nt][2] - m1);
        acc[nt][3] = __expf(acc[nt][3] - m1);
        s0 += acc[nt][0] + acc[nt][1];
        s1 += acc[nt][2] + acc[nt][3];
    }
#pragma unroll
    for (int off = 2; off >= 1; off >>= 1) {
        s0 += __shfl_xor_sync(0xffffffffu, s0, off);
        s1 += __shfl_xor_sync(0xffffffffu, s1, off);
    }
    const float inv0 = 1.0f / s0;
    const float inv1 = 1.0f / s1;

    // ---- prefetch residual (hides LDG latency under the PV loop) ----
    float* op = out + ((size_t)b * Sn) * HDn + h * Dn;
    float2 res0[8], res1[8];
#pragma unroll
    for (int nt = 0; nt < 8; ++nt) {
        const int d = nt * 8 + tg * 2;
        res0[nt] = *(const float2*)(op + (size_t)r0 * HDn + d);
        res1[nt] = *(const float2*)(op + (size_t)(r0 + 8) * HDn + d);
    }

    __syncthreads();   // all warps done reading SQ/SK before SP overlays them

#pragma unroll
    for (int nt = 0; nt < 16; ++nt) {
        const int cl = nt * 8 + tg * 2;
        *(uint2*)&SP[r0 * PPs + cl] =
            make_uint2(f2tf32(acc[nt][0]), f2tf32(acc[nt][1]));
        *(uint2*)&SP[(r0 + 8) * PPs + cl] =
            make_uint2(f2tf32(acc[nt][2]), f2tf32(acc[nt][3]));
    }
    __syncthreads();

    // ---- O = P V ----
    float oacc[8][4];
#pragma unroll
    for (int nt = 0; nt < 8; ++nt)
#pragma unroll
        for (int j = 0; j < 4; ++j) oacc[nt][j] = 0.f;

    const uint32_t* Ap = SP + (wid * 16 + g) * PPs;
#pragma unroll
    for (int ks = 0; ks < 16; ++ks) {
        const int k0 = ks * 8;
        uint32_t af[4];
        af[0] = Ap[k0 + tg];
        af[1] = Ap[8 * PPs + k0 + tg];
        af[2] = Ap[k0 + tg + 4];
        af[3] = Ap[8 * PPs + k0 + tg + 4];
#pragma unroll
        for (int nt = 0; nt < 8; ++nt) {
            uint32_t bf[2];
            bf[0] = SV[(k0 + tg) * PV + nt * 8 + g];
            bf[1] = SV[(k0 + tg + 4) * PV + nt * 8 + g];
            mma_tf32(oacc[nt], af, bf);
        }
    }

    // ---- epilogue: normalize, +residual (prefetched), ReLU ----
#pragma unroll
    for (int nt = 0; nt < 8; ++nt) {
        const int d = nt * 8 + tg * 2;
        float x0 = res0[nt].x + oacc[nt][0] * inv0;
        float x1 = res0[nt].y + oacc[nt][1] * inv0;
        float x2 = res1[nt].x + oacc[nt][2] * inv1;
        float x3 = res1[nt].y + oacc[nt][3] * inv1;
        *(float2*)(op + (size_t)r0 * HDn + d) =
            make_float2(fmaxf(x0, 0.f), fmaxf(x1, 0.f));
        *(float2*)(op + (size_t)(r0 + 8) * HDn + d) =
            make_float2(fmaxf(x2, 0.f), fmaxf(x3, 0.f));
    }
}

// =============================================================================
extern "C" void kernel_launch(void* const* d_in, const int* in_sizes, int n_in,
                              void* d_out, int out_size)
{
    const float* X  = (const float*)d_in[0];
    const float* Wq = (const float*)d_in[1];
    const float* Wk = (const float*)d_in[2];
    const float* Wv = (const float*)d_in[3];
    const float* Wr = (const float*)d_in[4];
    float* out = (float*)d_out;

    const int proj_smem = 3 * SLOT_U * (int)sizeof(uint32_t);                // 98304
    const int attn_smem = (2 * 128 * PK + 128 * PV) * (int)sizeof(uint32_t); // 106496
    cudaFuncSetAttribute(proj_mma,
                         cudaFuncAttributeMaxDynamicSharedMemorySize, proj_smem);
    cudaFuncSetAttribute(attn_mma,
                         cudaFuncAttributeMaxDynamicSharedMemorySize, attn_smem);

    xconv_kernel<<<dim3(8, 1024), 256>>>(X);
    wtrans_kernel<<<dim3(8, 16), 256>>>(Wq, Wk, Wv, Wr);
    proj_mma<<<dim3(16, 1024), 128, proj_smem>>>(out);
    attn_mma<<<dim3(8, 1024), 256, attn_smem>>>(out);
}